// round 3
// baseline (speedup 1.0000x reference)
#include <cuda_runtime.h>

#define NTOK   131072          // H*W*D = 64*64*32
#define CCH    96
#define BB     2
#define TN     128             // tokens per tile
#define NTILE  1024            // tiles per batch (NTOK/TN = 131072/128)
#define NBLK   (BB*NTILE)      // 2048 tile blocks
#define NPART  1248            // 8*12*12 KV partials + 96 sum-exp(k) partials

// Scratch (static device globals: allocation-free)
__device__ float g_partial[NBLK * NPART];   // per-tile partial reductions (~10 MB)
__device__ float g_red[BB * NPART];         // reduced per batch
__device__ float g_ctx[BB * 1152];          // context[b][h][d][e] (12x12 per head)

// ---- packed f32x2 helpers (full-rate fp32 FMA on sm_103a) ----
__device__ __forceinline__ unsigned long long pack2(float x, float y) {
    unsigned long long r;
    asm("mov.b64 %0, {%1, %2};" : "=l"(r) : "f"(x), "f"(y));
    return r;
}
__device__ __forceinline__ void fma2(unsigned long long& d, unsigned long long a,
                                     unsigned long long b) {
    asm("fma.rn.f32x2 %0, %1, %2, %0;" : "+l"(d) : "l"(a), "l"(b));
}
__device__ __forceinline__ float2 unpack2(unsigned long long a) {
    float lo, hi;
    asm("mov.b64 {%0, %1}, %2;" : "=f"(lo), "=f"(hi) : "l"(a));
    return make_float2(lo, hi);
}

// =====================================================================
// Kernel A: per 128-token tile, compute k=Wk@x (exp'ed) and v=Wv@x,
// then per-tile partials: KV[h,d,e] = sum_n exp(k[n,d])*v[n,e],
// sumK[c] = sum_n exp(k[n,c]).
// =====================================================================
__global__ void __launch_bounds__(256, 1)
kv_kernel(const float* __restrict__ x,
          const float* __restrict__ Wk, const float* __restrict__ Wv)
{
    extern __shared__ float sm[];
    float* sX = sm;                   // [96][129] x tile (padded vs bank conflicts)
    float* sK = sX + 96 * 129;        // [96][129] exp(k) tile
    float* sV = sK + 96 * 129;        // [96][129] v tile
    float* sW = sV + 96 * 129;        // [96][98]  W transposed: sW[c*98+o]=W[o,c]

    const int tile = blockIdx.x;
    const int b    = tile >> 10;                 // NTILE = 1024 tiles per batch
    const int n0   = (tile & (NTILE - 1)) * TN;
    const int tid  = threadIdx.x;
    const int n    = tid & (TN - 1);
    const int half = tid >> 7;

    const float* xb = x + (size_t)b * CCH * NTOK + n0;
    for (int i = tid; i < CCH * TN; i += 256) {
        int c = i >> 7, nn = i & (TN - 1);
        sX[c * 129 + nn] = xb[(size_t)c * NTOK + nn];
    }
    for (int i = tid; i < CCH * CCH; i += 256)
        sW[(i % 96) * 98 + (i / 96)] = Wk[i];
    __syncthreads();

    const float* xrow = sX + n;

    // ---- k pass: 48 outputs via 24 packed-f32x2 accumulators ----
    {
        unsigned long long acc[24];
        #pragma unroll
        for (int j = 0; j < 24; j++) acc[j] = 0ull;
        #pragma unroll 4
        for (int c = 0; c < 96; c++) {
            float xv = xrow[c * 129];
            unsigned long long xv2 = pack2(xv, xv);
            const unsigned long long* w2 =
                (const unsigned long long*)(sW + c * 98 + half * 48);
            #pragma unroll
            for (int j = 0; j < 24; j++) fma2(acc[j], w2[j], xv2);
        }
        #pragma unroll
        for (int j = 0; j < 24; j++) {
            float2 v = unpack2(acc[j]);
            int o = half * 48 + 2 * j;
            sK[o * 129 + n]       = __expf(v.x);
            sK[(o + 1) * 129 + n] = __expf(v.y);
        }
    }
    __syncthreads();
    for (int i = tid; i < CCH * CCH; i += 256)
        sW[(i % 96) * 98 + (i / 96)] = Wv[i];
    __syncthreads();

    // ---- v pass ----
    {
        unsigned long long acc[24];
        #pragma unroll
        for (int j = 0; j < 24; j++) acc[j] = 0ull;
        #pragma unroll 4
        for (int c = 0; c < 96; c++) {
            float xv = xrow[c * 129];
            unsigned long long xv2 = pack2(xv, xv);
            const unsigned long long* w2 =
                (const unsigned long long*)(sW + c * 98 + half * 48);
            #pragma unroll
            for (int j = 0; j < 24; j++) fma2(acc[j], w2[j], xv2);
        }
        #pragma unroll
        for (int j = 0; j < 24; j++) {
            float2 v = unpack2(acc[j]);
            int o = half * 48 + 2 * j;
            sV[o * 129 + n]       = v.x;
            sV[(o + 1) * 129 + n] = v.y;
        }
    }
    __syncthreads();

    // ---- per-tile KV / sumK partials (deterministic) ----
    float* po = g_partial + (size_t)tile * NPART;
    for (int idx = tid; idx < NPART; idx += 256) {
        float a = 0.f;
        if (idx < 1152) {
            int h = idx / 144;
            int r = idx - h * 144;
            int d = r / 12;
            int e = r - d * 12;
            const float* pk = sK + (h * 12 + d) * 129;
            const float* pv = sV + (h * 12 + e) * 129;
            #pragma unroll 4
            for (int t = 0; t < TN; t++) a += pk[t] * pv[t];
        } else {
            const float* pk = sK + (idx - 1152) * 129;
            #pragma unroll 4
            for (int t = 0; t < TN; t++) a += pk[t];
        }
        po[idx] = a;
    }
}

// ===== Kernel B1: reduce tile partials per batch (fixed order) =====
__global__ void red_kernel()
{
    int idx = blockIdx.x * 256 + threadIdx.x;
    int b = blockIdx.y;
    if (idx >= NPART) return;
    float a = 0.f;
    const float* p = g_partial + (size_t)b * NTILE * NPART + idx;
    #pragma unroll 4
    for (int t = 0; t < NTILE; t++) a += p[(size_t)t * NPART];
    g_red[b * NPART + idx] = a;
}

// ===== Kernel B2: context[b,h,d,e] = KV[h,d,e] / sumK[h*12+d] =====
__global__ void ctx_kernel()
{
    int gid = blockIdx.x * 256 + threadIdx.x;
    if (gid >= BB * 1152) return;
    int b = gid / 1152;
    int r = gid - b * 1152;
    int h = r / 144;                 // head index
    int d = (r % 144) / 12;          // within-head dim
    int ch = h * 12 + d;             // global channel
    g_ctx[gid] = g_red[b * NPART + r] / g_red[b * NPART + 1152 + ch];
}

// =====================================================================
// Kernel C: q = Wq@x (recompute), softmax over head-dim (local in regs),
// attn = q' @ ctx per head, then out = Wproj @ attn, write [B,C,N].
// =====================================================================
__global__ void __launch_bounds__(256, 1)
out_kernel(const float* __restrict__ x, const float* __restrict__ Wq,
           const float* __restrict__ Wproj, float* __restrict__ out)
{
    extern __shared__ float sm[];
    float* sX   = sm;                  // [96][129]
    float* sA   = sX + 96 * 129;       // [128][97] attn tile [n][c]
    float* sW   = sA + 128 * 97;       // [96][98]  Wq then Wproj transposed
    float* sCtx = sW + 96 * 98;        // 1152 context for this batch

    const int tile = blockIdx.x;
    const int b    = tile >> 10;
    const int n0   = (tile & (NTILE - 1)) * TN;
    const int tid  = threadIdx.x;
    const int n    = tid & (TN - 1);
    const int half = tid >> 7;

    const float* xb = x + (size_t)b * CCH * NTOK + n0;
    for (int i = tid; i < CCH * TN; i += 256) {
        int c = i >> 7, nn = i & (TN - 1);
        sX[c * 129 + nn] = xb[(size_t)c * NTOK + nn];
    }
    for (int i = tid; i < CCH * CCH; i += 256)
        sW[(i % 96) * 98 + (i / 96)] = Wq[i];
    for (int i = tid; i < 1152; i += 256)
        sCtx[i] = g_ctx[b * 1152 + i];
    __syncthreads();

    // ---- q pass ----
    unsigned long long acc[24];
    #pragma unroll
    for (int j = 0; j < 24; j++) acc[j] = 0ull;
    const float* xrow = sX + n;
    #pragma unroll 4
    for (int c = 0; c < 96; c++) {
        float xv = xrow[c * 129];
        unsigned long long xv2 = pack2(xv, xv);
        const unsigned long long* w2 =
            (const unsigned long long*)(sW + c * 98 + half * 48);
        #pragma unroll
        for (int j = 0; j < 24; j++) fma2(acc[j], w2[j], xv2);
    }
    __syncthreads();   // all threads done reading Wq from sW

    // reload sW with Wproj while softmax/attn proceed in registers
    for (int i = tid; i < CCH * CCH; i += 256)
        sW[(i % 96) * 98 + (i / 96)] = Wproj[i];

    float q[48];
    #pragma unroll
    for (int j = 0; j < 24; j++) {
        float2 v = unpack2(acc[j]);
        q[2 * j] = v.x; q[2 * j + 1] = v.y;
    }

    // softmax over head-dim (12) + attn = q' @ ctx, per owned head
    #pragma unroll
    for (int hh = 0; hh < 4; hh++) {
        float* qh = q + hh * 12;
        float m = qh[0];
        #pragma unroll
        for (int i = 1; i < 12; i++) m = fmaxf(m, qh[i]);
        float e[12];
        float s = 0.f;
        #pragma unroll
        for (int i = 0; i < 12; i++) { e[i] = __expf(qh[i] - m); s += e[i]; }
        float inv = 1.f / s;
        int h = half * 4 + hh;
        const float* cx = sCtx + h * 144;
        #pragma unroll
        for (int ee = 0; ee < 12; ee++) {
            float a = 0.f;
            #pragma unroll
            for (int d = 0; d < 12; d++) a += e[d] * cx[d * 12 + ee];
            sA[n * 97 + half * 48 + hh * 12 + ee] = a * inv;
        }
    }
    __syncthreads();

    // ---- proj pass: out[o,n] = sum_c Wproj[o,c]*attn[n,c] ----
    unsigned long long acc2[24];
    #pragma unroll
    for (int j = 0; j < 24; j++) acc2[j] = 0ull;
    const float* arow = sA + n * 97;
    #pragma unroll 4
    for (int c = 0; c < 96; c++) {
        float av = arow[c];
        unsigned long long av2 = pack2(av, av);
        const unsigned long long* w2 =
            (const unsigned long long*)(sW + c * 98 + half * 48);
        #pragma unroll
        for (int j = 0; j < 24; j++) fma2(acc2[j], w2[j], av2);
    }

    float* ob = out + (size_t)b * CCH * NTOK + n0 + n;
    #pragma unroll
    for (int j = 0; j < 24; j++) {
        float2 v = unpack2(acc2[j]);
        int o = half * 48 + 2 * j;
        ob[(size_t)o * NTOK]       = v.x;
        ob[(size_t)(o + 1) * NTOK] = v.y;
    }
}

extern "C" void kernel_launch(void* const* d_in, const int* in_sizes, int n_in,
                              void* d_out, int out_size)
{
    const float* x  = (const float*)d_in[0];
    const float* Wq = (const float*)d_in[1];
    const float* Wk = (const float*)d_in[2];
    const float* Wv = (const float*)d_in[3];
    const float* Wp = (const float*)d_in[4];
    float* out = (float*)d_out;

    const size_t smA = (size_t)(3 * 96 * 129 + 96 * 98) * sizeof(float);           // ~182 KB
    const size_t smC = (size_t)(96 * 129 + 128 * 97 + 96 * 98 + 1152) * sizeof(float); // ~138 KB
    cudaFuncSetAttribute(kv_kernel,  cudaFuncAttributeMaxDynamicSharedMemorySize, (int)smA);
    cudaFuncSetAttribute(out_kernel, cudaFuncAttributeMaxDynamicSharedMemorySize, (int)smC);

    kv_kernel<<<NBLK, 256, smA>>>(x, Wk, Wv);
    red_kernel<<<dim3(5, BB), 256>>>();
    ctx_kernel<<<(BB * 1152 + 255) / 256, 256>>>();
    out_kernel<<<NBLK, 256, smC>>>(x, Wq, Wp, out);
}

// round 4
// speedup vs baseline: 1.1183x; 1.1183x over previous
#include <cuda_runtime.h>

#define NTOK   131072          // H*W*D
#define CCH    96
#define BB     2
#define TN     128             // tokens per tile
#define NTILE  1024            // NTOK/TN
#define NBLK   (BB*NTILE)      // 2048
#define NPART  1248            // 8*144 KV + 96 sumK
#define RS     132             // smem row stride (tokens), /4 aligned
#define WS     98              // weight row stride

__device__ float g_partial[NBLK * NPART];
__device__ float g_red[BB * NPART];
__device__ float g_ctx[BB * 1152];

typedef unsigned long long ull;

__device__ __forceinline__ ull pack2(float x, float y) {
    ull r; asm("mov.b64 %0, {%1, %2};" : "=l"(r) : "f"(x), "f"(y)); return r;
}
__device__ __forceinline__ void fma2(ull& d, ull a, ull b) {
    asm("fma.rn.f32x2 %0, %1, %2, %0;" : "+l"(d) : "l"(a), "l"(b));
}
__device__ __forceinline__ float2 unpack2(ull a) {
    float lo, hi; asm("mov.b64 {%0, %1}, %2;" : "=f"(lo), "=f"(hi) : "l"(a));
    return make_float2(lo, hi);
}

// =====================================================================
// Kernel A: one x sweep computes k AND v (register-tiled 4 tok x 12 ch),
// exp(k), v -> smem, then float4 partial reduction KV/sumK per tile.
// Thread map: tg = tid&31 (token group, 4 tokens), og = tid>>5 (head).
// =====================================================================
__global__ void __launch_bounds__(256, 1)
kv_kernel(const float* __restrict__ x,
          const float* __restrict__ Wk, const float* __restrict__ Wv)
{
    extern __shared__ float sm[];
    float* sK  = sm;                    // [96][RS]
    float* sV  = sK + 96 * RS;          // [96][RS]
    float* sWk = sV + 96 * RS;          // [96][WS] transposed
    float* sWv = sWk + 96 * WS;

    const int tile = blockIdx.x;
    const int b    = tile >> 10;
    const int n0   = (tile & (NTILE - 1)) * TN;
    const int tid  = threadIdx.x;
    const int tg   = tid & 31;
    const int og   = tid >> 5;          // head index 0..7
    const int nt   = tg * 4;

    for (int i = tid; i < CCH * CCH; i += 256) {
        int o = i / 96, c = i - o * 96;
        sWk[c * WS + o] = Wk[i];
        sWv[c * WS + o] = Wv[i];
    }
    __syncthreads();

    const float* xg = x + (size_t)b * CCH * NTOK + n0 + nt;

    ull ak[24], av[24];
    #pragma unroll
    for (int j = 0; j < 24; j++) { ak[j] = 0ull; av[j] = 0ull; }

    #pragma unroll 2
    for (int c = 0; c < 96; c++) {
        float4 xv = *(const float4*)(xg + (size_t)c * NTOK);
        ull x0 = pack2(xv.x, xv.x), x1 = pack2(xv.y, xv.y);
        ull x2 = pack2(xv.z, xv.z), x3 = pack2(xv.w, xv.w);
        const ull* wk2 = (const ull*)(sWk + c * WS + og * 12);
        const ull* wv2 = (const ull*)(sWv + c * WS + og * 12);
        #pragma unroll
        for (int j = 0; j < 6; j++) {
            ull wk = wk2[j], wv = wv2[j];
            fma2(ak[j * 4 + 0], wk, x0); fma2(ak[j * 4 + 1], wk, x1);
            fma2(ak[j * 4 + 2], wk, x2); fma2(ak[j * 4 + 3], wk, x3);
            fma2(av[j * 4 + 0], wv, x0); fma2(av[j * 4 + 1], wv, x1);
            fma2(av[j * 4 + 2], wv, x2); fma2(av[j * 4 + 3], wv, x3);
        }
    }

    // write exp(k), v tiles: channel o = og*12+2j(+1), tokens nt..nt+3 (float4)
    #pragma unroll
    for (int j = 0; j < 6; j++) {
        float2 k0 = unpack2(ak[j * 4 + 0]), k1 = unpack2(ak[j * 4 + 1]);
        float2 k2 = unpack2(ak[j * 4 + 2]), k3 = unpack2(ak[j * 4 + 3]);
        int o = og * 12 + 2 * j;
        *(float4*)(sK + o * RS + nt) =
            make_float4(__expf(k0.x), __expf(k1.x), __expf(k2.x), __expf(k3.x));
        *(float4*)(sK + (o + 1) * RS + nt) =
            make_float4(__expf(k0.y), __expf(k1.y), __expf(k2.y), __expf(k3.y));
        float2 v0 = unpack2(av[j * 4 + 0]), v1 = unpack2(av[j * 4 + 1]);
        float2 v2 = unpack2(av[j * 4 + 2]), v3 = unpack2(av[j * 4 + 3]);
        *(float4*)(sV + o * RS + nt)       = make_float4(v0.x, v1.x, v2.x, v3.x);
        *(float4*)(sV + (o + 1) * RS + nt) = make_float4(v0.y, v1.y, v2.y, v3.y);
    }
    __syncthreads();

    // per-tile partials (float4 vectorized, deterministic order)
    float* po = g_partial + (size_t)tile * NPART;
    for (int idx = tid; idx < NPART; idx += 256) {
        float a = 0.f;
        if (idx < 1152) {
            int h = idx / 144, r = idx - h * 144, d = r / 12, e = r - d * 12;
            const float4* pk = (const float4*)(sK + (h * 12 + d) * RS);
            const float4* pv = (const float4*)(sV + (h * 12 + e) * RS);
            #pragma unroll 4
            for (int t = 0; t < TN / 4; t++) {
                float4 A = pk[t], B = pv[t];
                a += A.x * B.x + A.y * B.y + A.z * B.z + A.w * B.w;
            }
        } else {
            const float4* pk = (const float4*)(sK + (idx - 1152) * RS);
            #pragma unroll 4
            for (int t = 0; t < TN / 4; t++) {
                float4 A = pk[t];
                a += A.x + A.y + A.z + A.w;
            }
        }
        po[idx] = a;
    }
}

// ===== reduce tile partials per batch (fixed order) =====
__global__ void red_kernel()
{
    int idx = blockIdx.x * 256 + threadIdx.x;
    int b = blockIdx.y;
    if (idx >= NPART) return;
    float a = 0.f;
    const float* p = g_partial + (size_t)b * NTILE * NPART + idx;
    #pragma unroll 4
    for (int t = 0; t < NTILE; t++) a += p[(size_t)t * NPART];
    g_red[b * NPART + idx] = a;
}

// ===== context[b,h,d,e] = KV[h,d,e] / sumK[h*12+d] =====
__global__ void ctx_kernel()
{
    int gid = blockIdx.x * 256 + threadIdx.x;
    if (gid >= BB * 1152) return;
    int b = gid / 1152;
    int r = gid - b * 1152;
    int h = r / 144, d = (r % 144) / 12;
    g_ctx[gid] = g_red[b * NPART + r] / g_red[b * NPART + 1152 + h * 12 + d];
}

// =====================================================================
// Kernel C: q GEMM (reg-tiled, direct LDG x) -> softmax(12) -> attn via
// ctx (f32x2) -> sA -> proj GEMM -> coalesced float4 stores.
// smem ~93KB -> 2 CTAs/SM.
// =====================================================================
__global__ void __launch_bounds__(256, 2)
out_kernel(const float* __restrict__ x, const float* __restrict__ Wq,
           const float* __restrict__ Wproj, float* __restrict__ out)
{
    extern __shared__ float sm[];
    float* sA   = sm;                   // [96][RS] attn (channel x token)
    float* sW   = sA + 96 * RS;         // [96][WS] Wq then Wproj (transposed)
    float* sCtx = sW + 96 * WS;         // 1152

    const int tile = blockIdx.x;
    const int b    = tile >> 10;
    const int n0   = (tile & (NTILE - 1)) * TN;
    const int tid  = threadIdx.x;
    const int tg   = tid & 31;
    const int og   = tid >> 5;
    const int nt   = tg * 4;

    for (int i = tid; i < CCH * CCH; i += 256) {
        int o = i / 96, c = i - o * 96;
        sW[c * WS + o] = Wq[i];
    }
    for (int i = tid; i < 1152; i += 256) sCtx[i] = g_ctx[b * 1152 + i];
    __syncthreads();

    const float* xg = x + (size_t)b * CCH * NTOK + n0 + nt;

    // ---- q GEMM ----
    ull aq[24];
    #pragma unroll
    for (int j = 0; j < 24; j++) aq[j] = 0ull;
    #pragma unroll 2
    for (int c = 0; c < 96; c++) {
        float4 xv = *(const float4*)(xg + (size_t)c * NTOK);
        ull x0 = pack2(xv.x, xv.x), x1 = pack2(xv.y, xv.y);
        ull x2 = pack2(xv.z, xv.z), x3 = pack2(xv.w, xv.w);
        const ull* w2 = (const ull*)(sW + c * WS + og * 12);
        #pragma unroll
        for (int j = 0; j < 6; j++) {
            ull w = w2[j];
            fma2(aq[j * 4 + 0], w, x0); fma2(aq[j * 4 + 1], w, x1);
            fma2(aq[j * 4 + 2], w, x2); fma2(aq[j * 4 + 3], w, x3);
        }
    }
    __syncthreads();    // all reads of Wq done

    // reload sW with Wproj (overlaps with softmax/attn below)
    for (int i = tid; i < CCH * CCH; i += 256) {
        int o = i / 96, c = i - o * 96;
        sW[c * WS + o] = Wproj[i];
    }

    // ---- softmax over head dim + attn = p @ ctx[og], per token ----
    const ull* cx2 = (const ull*)(sCtx + og * 144);   // [12][6] f32x2 rows
    #pragma unroll
    for (int t = 0; t < 4; t++) {
        float qv[12];
        #pragma unroll
        for (int j = 0; j < 6; j++) {
            float2 v = unpack2(aq[j * 4 + t]);
            qv[2 * j] = v.x; qv[2 * j + 1] = v.y;
        }
        float m = qv[0];
        #pragma unroll
        for (int i = 1; i < 12; i++) m = fmaxf(m, qv[i]);
        float p[12]; float s = 0.f;
        #pragma unroll
        for (int i = 0; i < 12; i++) { p[i] = __expf(qv[i] - m); s += p[i]; }
        float inv = 1.f / s;

        ull at[6];
        #pragma unroll
        for (int j = 0; j < 6; j++) at[j] = 0ull;
        #pragma unroll
        for (int d = 0; d < 12; d++) {
            ull pd = pack2(p[d], p[d]);
            #pragma unroll
            for (int j = 0; j < 6; j++) fma2(at[j], cx2[d * 6 + j], pd);
        }
        #pragma unroll
        for (int j = 0; j < 6; j++) {
            float2 v = unpack2(at[j]);
            int o = og * 12 + 2 * j;
            sA[o * RS + nt + t]       = v.x * inv;
            sA[(o + 1) * RS + nt + t] = v.y * inv;
        }
    }
    __syncthreads();

    // ---- proj GEMM: out[o][n] = sum_c Wp[o][c] * sA[c][n] ----
    ull ap[24];
    #pragma unroll
    for (int j = 0; j < 24; j++) ap[j] = 0ull;
    #pragma unroll 2
    for (int c = 0; c < 96; c++) {
        float4 av = *(const float4*)(sA + c * RS + nt);
        ull x0 = pack2(av.x, av.x), x1 = pack2(av.y, av.y);
        ull x2 = pack2(av.z, av.z), x3 = pack2(av.w, av.w);
        const ull* w2 = (const ull*)(sW + c * WS + og * 12);
        #pragma unroll
        for (int j = 0; j < 6; j++) {
            ull w = w2[j];
            fma2(ap[j * 4 + 0], w, x0); fma2(ap[j * 4 + 1], w, x1);
            fma2(ap[j * 4 + 2], w, x2); fma2(ap[j * 4 + 3], w, x3);
        }
    }

    float* ob = out + (size_t)b * CCH * NTOK + n0 + nt;
    #pragma unroll
    for (int j = 0; j < 6; j++) {
        float2 v0 = unpack2(ap[j * 4 + 0]), v1 = unpack2(ap[j * 4 + 1]);
        float2 v2 = unpack2(ap[j * 4 + 2]), v3 = unpack2(ap[j * 4 + 3]);
        int o = og * 12 + 2 * j;
        *(float4*)(ob + (size_t)o * NTOK)       = make_float4(v0.x, v1.x, v2.x, v3.x);
        *(float4*)(ob + (size_t)(o + 1) * NTOK) = make_float4(v0.y, v1.y, v2.y, v3.y);
    }
}

extern "C" void kernel_launch(void* const* d_in, const int* in_sizes, int n_in,
                              void* d_out, int out_size)
{
    const float* x  = (const float*)d_in[0];
    const float* Wq = (const float*)d_in[1];
    const float* Wk = (const float*)d_in[2];
    const float* Wv = (const float*)d_in[3];
    const float* Wp = (const float*)d_in[4];
    float* out = (float*)d_out;

    const size_t smA = (size_t)(2 * 96 * RS + 2 * 96 * WS) * sizeof(float);   // ~172.5 KB
    const size_t smC = (size_t)(96 * RS + 96 * WS + 1152) * sizeof(float);    // ~90.8 KB
    cudaFuncSetAttribute(kv_kernel,  cudaFuncAttributeMaxDynamicSharedMemorySize, (int)smA);
    cudaFuncSetAttribute(out_kernel, cudaFuncAttributeMaxDynamicSharedMemorySize, (int)smC);

    kv_kernel<<<NBLK, 256, smA>>>(x, Wk, Wv);
    red_kernel<<<dim3(5, BB), 256>>>();
    ctx_kernel<<<(BB * 1152 + 255) / 256, 256>>>();
    out_kernel<<<NBLK, 256, smC>>>(x, Wq, Wp, out);
}

// round 5
// speedup vs baseline: 1.4008x; 1.2526x over previous
#include <cuda_runtime.h>

#define NTOK   131072          // H*W*D
#define CCH    96
#define BB     2
#define TN     128             // tokens per tile
#define NTILE  1024            // NTOK/TN
#define NBLK   (BB*NTILE)      // 2048
#define NPART  1248            // 8*144 KV + 96 sumK
#define RS     132             // smem tile row stride
#define WS     98              // weight row stride

__device__ float g_partial[NBLK * NPART];
__device__ float g_red[BB * NPART];
__device__ float g_ctx[BB * 1152];
__device__ float g_p[(size_t)BB * CCH * NTOK];   // softmax(q), channel-major

typedef unsigned long long ull;

__device__ __forceinline__ ull pack2(float x, float y) {
    ull r; asm("mov.b64 %0, {%1, %2};" : "=l"(r) : "f"(x), "f"(y)); return r;
}
__device__ __forceinline__ void fma2(ull& d, ull a, ull b) {
    asm("fma.rn.f32x2 %0, %1, %2, %0;" : "+l"(d) : "l"(a), "l"(b));
}
__device__ __forceinline__ float2 unpack2(ull a) {
    float lo, hi; asm("mov.b64 {%0, %1}, %2;" : "=f"(lo), "=f"(hi) : "l"(a));
    return make_float2(lo, hi);
}

// =====================================================================
// Kernel A: ONE x sweep -> q,k,v GEMMs (reg-tiled 2 tok x 12 ch).
// softmax(q) -> g_p; exp(k),v -> smem -> per-tile KV/sumK partials.
// 512 threads: tg = tid&63 (2 tokens each), og = tid>>6 (head).
// =====================================================================
__global__ void __launch_bounds__(512, 1)
qkv_kernel(const float* __restrict__ x, const float* __restrict__ Wq,
           const float* __restrict__ Wk, const float* __restrict__ Wv)
{
    extern __shared__ float sm[];
    float* sK  = sm;                    // [96][RS]
    float* sV  = sK + 96 * RS;          // [96][RS]
    float* sWq = sV + 96 * RS;          // [96][WS] transposed
    float* sWk = sWq + 96 * WS;
    float* sWv = sWk + 96 * WS;

    const int tile = blockIdx.x;
    const int b    = tile >> 10;
    const int n0   = (tile & (NTILE - 1)) * TN;
    const int tid  = threadIdx.x;
    const int tg   = tid & 63;
    const int og   = tid >> 6;          // head 0..7
    const int nt   = tg * 2;

    for (int i = tid; i < CCH * CCH; i += 512) {
        int o = i / 96, c = i - o * 96;
        sWq[c * WS + o] = Wq[i];
        sWk[c * WS + o] = Wk[i];
        sWv[c * WS + o] = Wv[i];
    }
    __syncthreads();

    const float* xg = x + (size_t)b * CCH * NTOK + n0 + nt;

    // accumulators: [channel-pair j=0..5][token t=0..1]
    ull aq[12], ak[12], av[12];
    #pragma unroll
    for (int j = 0; j < 12; j++) { aq[j] = 0ull; ak[j] = 0ull; av[j] = 0ull; }

    #pragma unroll 4
    for (int c = 0; c < 96; c++) {
        float2 xv = *(const float2*)(xg + (size_t)c * NTOK);
        ull x0 = pack2(xv.x, xv.x), x1 = pack2(xv.y, xv.y);
        const ull* wq2 = (const ull*)(sWq + c * WS + og * 12);
        const ull* wk2 = (const ull*)(sWk + c * WS + og * 12);
        const ull* wv2 = (const ull*)(sWv + c * WS + og * 12);
        #pragma unroll
        for (int j = 0; j < 6; j++) {
            ull wq = wq2[j], wk = wk2[j], wv = wv2[j];
            fma2(aq[j * 2 + 0], wq, x0); fma2(aq[j * 2 + 1], wq, x1);
            fma2(ak[j * 2 + 0], wk, x0); fma2(ak[j * 2 + 1], wk, x1);
            fma2(av[j * 2 + 0], wv, x0); fma2(av[j * 2 + 1], wv, x1);
        }
    }

    // ---- softmax(q) over head dim, per token; store p (float2/channel) ----
    float p0[12], p1[12];
    #pragma unroll
    for (int t = 0; t < 2; t++) {
        float qv[12];
        #pragma unroll
        for (int j = 0; j < 6; j++) {
            float2 v = unpack2(aq[j * 2 + t]);
            qv[2 * j] = v.x; qv[2 * j + 1] = v.y;
        }
        float m = qv[0];
        #pragma unroll
        for (int i = 1; i < 12; i++) m = fmaxf(m, qv[i]);
        float s = 0.f; float* pp = t ? p1 : p0;
        #pragma unroll
        for (int i = 0; i < 12; i++) { pp[i] = __expf(qv[i] - m); s += pp[i]; }
        float inv = 1.f / s;
        #pragma unroll
        for (int i = 0; i < 12; i++) pp[i] *= inv;
    }
    float* gp = g_p + (size_t)b * CCH * NTOK + n0 + nt;
    #pragma unroll
    for (int i = 0; i < 12; i++)
        *(float2*)(gp + (size_t)(og * 12 + i) * NTOK) = make_float2(p0[i], p1[i]);

    // ---- exp(k), v -> smem (float2 = 2 tokens per channel) ----
    #pragma unroll
    for (int j = 0; j < 6; j++) {
        float2 k0 = unpack2(ak[j * 2 + 0]), k1 = unpack2(ak[j * 2 + 1]);
        float2 v0 = unpack2(av[j * 2 + 0]), v1 = unpack2(av[j * 2 + 1]);
        int o = og * 12 + 2 * j;
        *(float2*)(sK + o * RS + nt)       = make_float2(__expf(k0.x), __expf(k1.x));
        *(float2*)(sK + (o + 1) * RS + nt) = make_float2(__expf(k0.y), __expf(k1.y));
        *(float2*)(sV + o * RS + nt)       = make_float2(v0.x, v1.x);
        *(float2*)(sV + (o + 1) * RS + nt) = make_float2(v0.y, v1.y);
    }
    __syncthreads();

    // ---- per-tile KV / sumK partials ----
    float* po = g_partial + (size_t)tile * NPART;
    for (int idx = tid; idx < NPART; idx += 512) {
        float a = 0.f;
        if (idx < 1152) {
            int h = idx / 144, r = idx - h * 144, d = r / 12, e = r - d * 12;
            const float4* pk = (const float4*)(sK + (h * 12 + d) * RS);
            const float4* pv = (const float4*)(sV + (h * 12 + e) * RS);
            #pragma unroll 4
            for (int t = 0; t < TN / 4; t++) {
                float4 A = pk[t], B = pv[t];
                a += A.x * B.x + A.y * B.y + A.z * B.z + A.w * B.w;
            }
        } else {
            const float4* pk = (const float4*)(sK + (idx - 1152) * RS);
            #pragma unroll 4
            for (int t = 0; t < TN / 4; t++) {
                float4 A = pk[t];
                a += A.x + A.y + A.z + A.w;
            }
        }
        po[idx] = a;
    }
}

// ===== reduce tile partials per batch (fixed order) =====
__global__ void red_kernel()
{
    int idx = blockIdx.x * 256 + threadIdx.x;
    int b = blockIdx.y;
    if (idx >= NPART) return;
    float a = 0.f;
    const float* p = g_partial + (size_t)b * NTILE * NPART + idx;
    #pragma unroll 4
    for (int t = 0; t < NTILE; t++) a += p[(size_t)t * NPART];
    g_red[b * NPART + idx] = a;
}

// ===== context[b,h,d,e] = KV[h,d,e] / sumK[h*12+d] =====
__global__ void ctx_kernel()
{
    int gid = blockIdx.x * 256 + threadIdx.x;
    if (gid >= BB * 1152) return;
    int b = gid / 1152;
    int r = gid - b * 1152;
    int h = r / 144, d = (r % 144) / 12;
    g_ctx[gid] = g_red[b * NPART + r] / g_red[b * NPART + 1152 + h * 12 + d];
}

// =====================================================================
// Kernel C: load p tile -> attn = p @ ctx IN-PLACE in tile -> proj GEMM.
// 256 threads, 4 tokens/thread; smem ~91KB -> 2 CTAs/SM.
// =====================================================================
__global__ void __launch_bounds__(256, 2)
out_kernel(const float* __restrict__ Wproj, float* __restrict__ out)
{
    extern __shared__ float sm[];
    float* sP   = sm;                   // [96][RS] p tile, overwritten by attn
    float* sW   = sP + 96 * RS;         // [96][WS] Wproj transposed
    float* sCtx = sW + 96 * WS;         // 1152

    const int tile = blockIdx.x;
    const int b    = tile >> 10;
    const int n0   = (tile & (NTILE - 1)) * TN;
    const int tid  = threadIdx.x;
    const int tg   = tid & 31;
    const int og   = tid >> 5;
    const int nt   = tg * 4;

    const float* gp = g_p + (size_t)b * CCH * NTOK + n0;
    for (int i = tid; i < CCH * TN; i += 256) {
        int c = i >> 7, nn = i & (TN - 1);
        sP[c * RS + nn] = gp[(size_t)c * NTOK + nn];
    }
    for (int i = tid; i < CCH * CCH; i += 256) {
        int o = i / 96, c = i - o * 96;
        sW[c * WS + o] = Wproj[i];
    }
    for (int i = tid; i < 1152; i += 256) sCtx[i] = g_ctx[b * 1152 + i];
    __syncthreads();

    // ---- attn = p @ ctx, in-place per (head, token) slice ----
    const ull* cx2 = (const ull*)(sCtx + og * 144);   // [12 d][6 e-pairs]
    #pragma unroll
    for (int t = 0; t < 4; t++) {
        float pv[12];
        #pragma unroll
        for (int d = 0; d < 12; d++) pv[d] = sP[(og * 12 + d) * RS + nt + t];
        ull at[6];
        #pragma unroll
        for (int j = 0; j < 6; j++) at[j] = 0ull;
        #pragma unroll
        for (int d = 0; d < 12; d++) {
            ull pd = pack2(pv[d], pv[d]);
            #pragma unroll
            for (int j = 0; j < 6; j++) fma2(at[j], cx2[d * 6 + j], pd);
        }
        #pragma unroll
        for (int j = 0; j < 6; j++) {
            float2 v = unpack2(at[j]);
            sP[(og * 12 + 2 * j) * RS + nt + t]     = v.x;
            sP[(og * 12 + 2 * j + 1) * RS + nt + t] = v.y;
        }
    }
    __syncthreads();

    // ---- proj GEMM: out[o][n] = sum_c Wp[o][c] * attn[c][n] ----
    ull ap[24];
    #pragma unroll
    for (int j = 0; j < 24; j++) ap[j] = 0ull;
    #pragma unroll 2
    for (int c = 0; c < 96; c++) {
        float4 av = *(const float4*)(sP + c * RS + nt);
        ull x0 = pack2(av.x, av.x), x1 = pack2(av.y, av.y);
        ull x2 = pack2(av.z, av.z), x3 = pack2(av.w, av.w);
        const ull* w2 = (const ull*)(sW + c * WS + og * 12);
        #pragma unroll
        for (int j = 0; j < 6; j++) {
            ull w = w2[j];
            fma2(ap[j * 4 + 0], w, x0); fma2(ap[j * 4 + 1], w, x1);
            fma2(ap[j * 4 + 2], w, x2); fma2(ap[j * 4 + 3], w, x3);
        }
    }

    float* ob = out + (size_t)b * CCH * NTOK + n0 + nt;
    #pragma unroll
    for (int j = 0; j < 6; j++) {
        float2 v0 = unpack2(ap[j * 4 + 0]), v1 = unpack2(ap[j * 4 + 1]);
        float2 v2 = unpack2(ap[j * 4 + 2]), v3 = unpack2(ap[j * 4 + 3]);
        int o = og * 12 + 2 * j;
        *(float4*)(ob + (size_t)o * NTOK)       = make_float4(v0.x, v1.x, v2.x, v3.x);
        *(float4*)(ob + (size_t)(o + 1) * NTOK) = make_float4(v0.y, v1.y, v2.y, v3.y);
    }
}

extern "C" void kernel_launch(void* const* d_in, const int* in_sizes, int n_in,
                              void* d_out, int out_size)
{
    const float* x  = (const float*)d_in[0];
    const float* Wq = (const float*)d_in[1];
    const float* Wk = (const float*)d_in[2];
    const float* Wv = (const float*)d_in[3];
    const float* Wp = (const float*)d_in[4];
    float* out = (float*)d_out;

    const size_t smA = (size_t)(2 * 96 * RS + 3 * 96 * WS) * sizeof(float);   // ~209 KB
    const size_t smC = (size_t)(96 * RS + 96 * WS + 1152) * sizeof(float);    // ~91 KB
    cudaFuncSetAttribute(qkv_kernel, cudaFuncAttributeMaxDynamicSharedMemorySize, (int)smA);
    cudaFuncSetAttribute(out_kernel, cudaFuncAttributeMaxDynamicSharedMemorySize, (int)smC);

    qkv_kernel<<<NBLK, 512, smA>>>(x, Wq, Wk, Wv);
    red_kernel<<<dim3(5, BB), 256>>>();
    ctx_kernel<<<(BB * 1152 + 255) / 256, 256>>>();
    out_kernel<<<NBLK, 256, smC>>>(Wp, out);
}

// round 6
// speedup vs baseline: 1.4077x; 1.0049x over previous
#include <cuda_runtime.h>

#define NTOK   131072          // H*W*D
#define CCH    96
#define BB     2
#define TN     128             // tokens per tile
#define NTILE  1024            // NTOK/TN
#define NBLK   (BB*NTILE)      // 2048
#define NPART  1248            // 8*144 KV + 96 sumK
#define RS     132             // smem tile row stride (floats)
#define R4     (RS/4)          // row stride in float4s
#define WS     100             // weight row stride (16B-aligned rows)

__device__ float g_partial[NBLK * NPART];
__device__ float g_red[BB * NPART];
__device__ float g_ctx[BB * 1152];
__device__ float g_p[(size_t)BB * CCH * NTOK];   // softmax(q), channel-major

typedef unsigned long long ull;

__device__ __forceinline__ ull pack2(float x, float y) {
    ull r; asm("mov.b64 %0, {%1, %2};" : "=l"(r) : "f"(x), "f"(y)); return r;
}
__device__ __forceinline__ void fma2(ull& d, ull a, ull b) {
    asm("fma.rn.f32x2 %0, %1, %2, %0;" : "+l"(d) : "l"(a), "l"(b));
}
__device__ __forceinline__ float2 unpack2(ull a) {
    float lo, hi; asm("mov.b64 {%0, %1}, %2;" : "=f"(lo), "=f"(hi) : "l"(a));
    return make_float2(lo, hi);
}

// =====================================================================
// Kernel A: ONE x sweep -> q,k,v GEMMs (reg-tiled 2 tok x 12 ch).
// softmax(q) -> g_p; exp(k),v -> smem -> blocked KV/sumK partials.
// 512 threads: tg = tid&63 (2 tokens each), og = tid>>6 (head).
// =====================================================================
__global__ void __launch_bounds__(512, 1)
qkv_kernel(const float* __restrict__ x, const float* __restrict__ Wq,
           const float* __restrict__ Wk, const float* __restrict__ Wv)
{
    extern __shared__ float sm[];
    float* sK  = sm;                    // [96][RS]
    float* sV  = sK + 96 * RS;          // [96][RS]
    float* sWq = sV + 96 * RS;          // [96][WS] transposed
    float* sWk = sWq + 96 * WS;
    float* sWv = sWk + 96 * WS;

    const int tile = blockIdx.x;
    const int b    = tile >> 10;
    const int n0   = (tile & (NTILE - 1)) * TN;
    const int tid  = threadIdx.x;
    const int tg   = tid & 63;
    const int og   = tid >> 6;          // head 0..7
    const int nt   = tg * 2;

    for (int i = tid; i < CCH * CCH; i += 512) {
        int o = i / 96, c = i - o * 96;
        sWq[c * WS + o] = Wq[i];
        sWk[c * WS + o] = Wk[i];
        sWv[c * WS + o] = Wv[i];
    }
    __syncthreads();

    const float* xg = x + (size_t)b * CCH * NTOK + n0 + nt;

    // accumulators: [channel-pair j=0..5][token t=0..1]
    ull aq[12], ak[12], av[12];
    #pragma unroll
    for (int j = 0; j < 12; j++) { aq[j] = 0ull; ak[j] = 0ull; av[j] = 0ull; }

    #pragma unroll 4
    for (int c = 0; c < 96; c++) {
        float2 xv = *(const float2*)(xg + (size_t)c * NTOK);
        ull x0 = pack2(xv.x, xv.x), x1 = pack2(xv.y, xv.y);
        const ulonglong2* wq4 = (const ulonglong2*)(sWq + c * WS + og * 12);
        const ulonglong2* wk4 = (const ulonglong2*)(sWk + c * WS + og * 12);
        const ulonglong2* wv4 = (const ulonglong2*)(sWv + c * WS + og * 12);
        #pragma unroll
        for (int jj = 0; jj < 3; jj++) {
            ulonglong2 wq = wq4[jj], wk = wk4[jj], wv = wv4[jj];
            fma2(aq[jj * 4 + 0], wq.x, x0); fma2(aq[jj * 4 + 1], wq.x, x1);
            fma2(aq[jj * 4 + 2], wq.y, x0); fma2(aq[jj * 4 + 3], wq.y, x1);
            fma2(ak[jj * 4 + 0], wk.x, x0); fma2(ak[jj * 4 + 1], wk.x, x1);
            fma2(ak[jj * 4 + 2], wk.y, x0); fma2(ak[jj * 4 + 3], wk.y, x1);
            fma2(av[jj * 4 + 0], wv.x, x0); fma2(av[jj * 4 + 1], wv.x, x1);
            fma2(av[jj * 4 + 2], wv.y, x0); fma2(av[jj * 4 + 3], wv.y, x1);
        }
    }

    // ---- softmax(q) over head dim, per token; store p ----
    float p0[12], p1[12];
    #pragma unroll
    for (int t = 0; t < 2; t++) {
        float qv[12];
        #pragma unroll
        for (int j = 0; j < 6; j++) {
            float2 v = unpack2(aq[(j >> 1) * 4 + (j & 1) * 2 + t]);
            qv[2 * j] = v.x; qv[2 * j + 1] = v.y;
        }
        float m = qv[0];
        #pragma unroll
        for (int i = 1; i < 12; i++) m = fmaxf(m, qv[i]);
        float s = 0.f; float* pp = t ? p1 : p0;
        #pragma unroll
        for (int i = 0; i < 12; i++) { pp[i] = __expf(qv[i] - m); s += pp[i]; }
        float inv = 1.f / s;
        #pragma unroll
        for (int i = 0; i < 12; i++) pp[i] *= inv;
    }
    float* gp = g_p + (size_t)b * CCH * NTOK + n0 + nt;
    #pragma unroll
    for (int i = 0; i < 12; i++)
        *(float2*)(gp + (size_t)(og * 12 + i) * NTOK) = make_float2(p0[i], p1[i]);

    // ---- exp(k), v -> smem (float2 = 2 tokens per channel) ----
    #pragma unroll
    for (int jj = 0; jj < 3; jj++) {
        #pragma unroll
        for (int jh = 0; jh < 2; jh++) {
            float2 k0 = unpack2(ak[jj * 4 + jh * 2 + 0]);
            float2 k1 = unpack2(ak[jj * 4 + jh * 2 + 1]);
            float2 v0 = unpack2(av[jj * 4 + jh * 2 + 0]);
            float2 v1 = unpack2(av[jj * 4 + jh * 2 + 1]);
            int o = og * 12 + jj * 4 + jh * 2;
            *(float2*)(sK + o * RS + nt)       = make_float2(__expf(k0.x), __expf(k1.x));
            *(float2*)(sK + (o + 1) * RS + nt) = make_float2(__expf(k0.y), __expf(k1.y));
            *(float2*)(sV + o * RS + nt)       = make_float2(v0.x, v1.x);
            *(float2*)(sV + (o + 1) * RS + nt) = make_float2(v0.y, v1.y);
        }
    }
    __syncthreads();

    // ---- blocked KV / sumK partials: 72 KV tasks (4x4 blocks) + 24 sumK ----
    float* po = g_partial + (size_t)tile * NPART;
    if (tid < 72) {
        int h = tid / 9, r = tid - h * 9, db = r / 3, eb = r - db * 3;
        const float4* pk0 = (const float4*)(sK + (h * 12 + db * 4) * RS);
        const float4* pv0 = (const float4*)(sV + (h * 12 + eb * 4) * RS);
        ull acc[16];
        #pragma unroll
        for (int i = 0; i < 16; i++) acc[i] = 0ull;
        #pragma unroll 2
        for (int t = 0; t < TN / 4; t++) {
            float4 K[4], V[4];
            #pragma unroll
            for (int i = 0; i < 4; i++) { K[i] = pk0[i * R4 + t]; V[i] = pv0[i * R4 + t]; }
            ull Kxy[4], Kzw[4], Vxy[4], Vzw[4];
            #pragma unroll
            for (int i = 0; i < 4; i++) {
                Kxy[i] = pack2(K[i].x, K[i].y); Kzw[i] = pack2(K[i].z, K[i].w);
                Vxy[i] = pack2(V[i].x, V[i].y); Vzw[i] = pack2(V[i].z, V[i].w);
            }
            #pragma unroll
            for (int i = 0; i < 4; i++)
                #pragma unroll
                for (int j = 0; j < 4; j++) {
                    fma2(acc[i * 4 + j], Kxy[i], Vxy[j]);
                    fma2(acc[i * 4 + j], Kzw[i], Vzw[j]);
                }
        }
        #pragma unroll
        for (int i = 0; i < 4; i++)
            #pragma unroll
            for (int j = 0; j < 4; j++) {
                float2 v = unpack2(acc[i * 4 + j]);
                po[h * 144 + (db * 4 + i) * 12 + eb * 4 + j] = v.x + v.y;
            }
    } else if (tid < 96) {
        int c0 = (tid - 72) * 4;
        float a[4] = {0.f, 0.f, 0.f, 0.f};
        #pragma unroll 2
        for (int t = 0; t < TN / 4; t++) {
            #pragma unroll
            for (int i = 0; i < 4; i++) {
                float4 K = ((const float4*)(sK + (c0 + i) * RS))[t];
                a[i] += K.x + K.y + K.z + K.w;
            }
        }
        #pragma unroll
        for (int i = 0; i < 4; i++) po[1152 + c0 + i] = a[i];
    }
}

// ===== reduce tile partials per batch (fixed order) =====
__global__ void red_kernel()
{
    int idx = blockIdx.x * 256 + threadIdx.x;
    int b = blockIdx.y;
    if (idx >= NPART) return;
    float a = 0.f;
    const float* p = g_partial + (size_t)b * NTILE * NPART + idx;
    #pragma unroll 4
    for (int t = 0; t < NTILE; t++) a += p[(size_t)t * NPART];
    g_red[b * NPART + idx] = a;
}

// ===== context[b,h,d,e] = KV[h,d,e] / sumK[h*12+d] =====
__global__ void ctx_kernel()
{
    int gid = blockIdx.x * 256 + threadIdx.x;
    if (gid >= BB * 1152) return;
    int b = gid / 1152;
    int r = gid - b * 1152;
    int h = r / 144, d = (r % 144) / 12;
    g_ctx[gid] = g_red[b * NPART + r] / g_red[b * NPART + 1152 + h * 12 + d];
}

// =====================================================================
// Kernel C: load p tile -> attn = p @ ctx IN-PLACE -> proj GEMM.
// 256 threads, 4 tokens/thread; smem ~92KB -> 2 CTAs/SM.
// =====================================================================
__global__ void __launch_bounds__(256, 2)
out_kernel(const float* __restrict__ Wproj, float* __restrict__ out)
{
    extern __shared__ float sm[];
    float* sP   = sm;                   // [96][RS] p tile, overwritten by attn
    float* sW   = sP + 96 * RS;         // [96][WS] Wproj transposed
    float* sCtx = sW + 96 * WS;         // 1152

    const int tile = blockIdx.x;
    const int b    = tile >> 10;
    const int n0   = (tile & (NTILE - 1)) * TN;
    const int tid  = threadIdx.x;
    const int tg   = tid & 31;
    const int og   = tid >> 5;
    const int nt   = tg * 4;

    const float* gp = g_p + (size_t)b * CCH * NTOK + n0;
    for (int i = tid; i < CCH * TN; i += 256) {
        int c = i >> 7, nn = i & (TN - 1);
        sP[c * RS + nn] = gp[(size_t)c * NTOK + nn];
    }
    for (int i = tid; i < CCH * CCH; i += 256) {
        int o = i / 96, c = i - o * 96;
        sW[c * WS + o] = Wproj[i];
    }
    for (int i = tid; i < 1152; i += 256) sCtx[i] = g_ctx[b * 1152 + i];
    __syncthreads();

    // ---- attn = p @ ctx, in-place per (head, token) slice ----
    const ull* cx2 = (const ull*)(sCtx + og * 144);   // [12 d][6 e-pairs]
    #pragma unroll
    for (int t = 0; t < 4; t++) {
        float pv[12];
        #pragma unroll
        for (int d = 0; d < 12; d++) pv[d] = sP[(og * 12 + d) * RS + nt + t];
        ull at[6];
        #pragma unroll
        for (int j = 0; j < 6; j++) at[j] = 0ull;
        #pragma unroll
        for (int d = 0; d < 12; d++) {
            ull pd = pack2(pv[d], pv[d]);
            #pragma unroll
            for (int j = 0; j < 6; j++) fma2(at[j], cx2[d * 6 + j], pd);
        }
        #pragma unroll
        for (int j = 0; j < 6; j++) {
            float2 v = unpack2(at[j]);
            sP[(og * 12 + 2 * j) * RS + nt + t]     = v.x;
            sP[(og * 12 + 2 * j + 1) * RS + nt + t] = v.y;
        }
    }
    __syncthreads();

    // ---- proj GEMM: out[o][n] = sum_c Wp[o][c] * attn[c][n] ----
    ull ap[24];
    #pragma unroll
    for (int j = 0; j < 24; j++) ap[j] = 0ull;
    #pragma unroll 2
    for (int c = 0; c < 96; c++) {
        float4 av = *(const float4*)(sP + c * RS + nt);
        ull x0 = pack2(av.x, av.x), x1 = pack2(av.y, av.y);
        ull x2 = pack2(av.z, av.z), x3 = pack2(av.w, av.w);
        const ulonglong2* w4 = (const ulonglong2*)(sW + c * WS + og * 12);
        #pragma unroll
        for (int jj = 0; jj < 3; jj++) {
            ulonglong2 w = w4[jj];
            fma2(ap[jj * 8 + 0], w.x, x0); fma2(ap[jj * 8 + 1], w.x, x1);
            fma2(ap[jj * 8 + 2], w.x, x2); fma2(ap[jj * 8 + 3], w.x, x3);
            fma2(ap[jj * 8 + 4], w.y, x0); fma2(ap[jj * 8 + 5], w.y, x1);
            fma2(ap[jj * 8 + 6], w.y, x2); fma2(ap[jj * 8 + 7], w.y, x3);
        }
    }

    float* ob = out + (size_t)b * CCH * NTOK + n0 + nt;
    #pragma unroll
    for (int jj = 0; jj < 3; jj++) {
        #pragma unroll
        for (int jh = 0; jh < 2; jh++) {
            float2 v0 = unpack2(ap[jj * 8 + jh * 4 + 0]);
            float2 v1 = unpack2(ap[jj * 8 + jh * 4 + 1]);
            float2 v2 = unpack2(ap[jj * 8 + jh * 4 + 2]);
            float2 v3 = unpack2(ap[jj * 8 + jh * 4 + 3]);
            int o = og * 12 + jj * 4 + jh * 2;  // wait: jh indexes w.x/w.y pair
            // w.x -> channel o, w.y -> channel o+1; acc layout: jh*4 selects x/y
            o = og * 12 + jj * 4 + jh * 2;
            *(float4*)(ob + (size_t)o * NTOK)       = make_float4(v0.x, v1.x, v2.x, v3.x);
            *(float4*)(ob + (size_t)(o + 1) * NTOK) = make_float4(v0.y, v1.y, v2.y, v3.y);
        }
    }
}

extern "C" void kernel_launch(void* const* d_in, const int* in_sizes, int n_in,
                              void* d_out, int out_size)
{
    const float* x  = (const float*)d_in[0];
    const float* Wq = (const float*)d_in[1];
    const float* Wk = (const float*)d_in[2];
    const float* Wv = (const float*)d_in[3];
    const float* Wp = (const float*)d_in[4];
    float* out = (float*)d_out;

    const size_t smA = (size_t)(2 * 96 * RS + 3 * 96 * WS) * sizeof(float);   // 216,576 B
    const size_t smC = (size_t)(96 * RS + 96 * WS + 1152) * sizeof(float);    // 93,696 B
    cudaFuncSetAttribute(qkv_kernel, cudaFuncAttributeMaxDynamicSharedMemorySize, (int)smA);
    cudaFuncSetAttribute(out_kernel, cudaFuncAttributeMaxDynamicSharedMemorySize, (int)smC);

    qkv_kernel<<<NBLK, 512, smA>>>(x, Wq, Wk, Wv);
    red_kernel<<<dim3(5, BB), 256>>>();
    ctx_kernel<<<(BB * 1152 + 255) / 256, 256>>>();
    out_kernel<<<NBLK, 256, smC>>>(Wp, out);
}